// round 16
// baseline (speedup 1.0000x reference)
#include <cuda_runtime.h>
#include <cuda_bf16.h>

// Inputs (metadata order):
//   d_in[0] = x            float32 [65536]
//   d_in[1] = edge_weights float32 [16777216]
//   d_in[2] = bias         float32 [65536]
//   d_in[3] = src          int32   [16777216]
//   d_in[4] = dst          int32   [16777216]
// Output: out[i] = bias[i] + sum_{e: dst[e]==i} x[src[e]]*edge_weights[e]
//
// R16: scatter frozen (R15 exact: unroll-4, REPLICAS=16 knee, bias prologue,
// __ldcs streams, smem gather for 87.5% of x; measured ~98us, at the LTS
// fp32-RMW cap ~101us). Reduce micro-tune: RPG 4 -> 8 (RGROUPS=2, 32768
// threads, MLP=8) to shrink the latency-exposed fraction of its ~6.1us.

#define NODES      65536
#define REPLICAS   16
#define RGROUPS    2
#define RPG        (REPLICAS / RGROUPS)   // 8 replicas per thread
#define COLS4      (NODES / 4)            // 16384 float4 columns
#define SMEM_NODES 57344                  // 224KB of x in smem
#define SMEM_BYTES (SMEM_NODES * 4)

__device__ float g_rep[REPLICAS * NODES];   // 4MB scratch, zero-initialized

__global__ __launch_bounds__(1024) void scatter_smem_rep_kernel(
        const float* __restrict__ x,
        const float* __restrict__ ew,
        const int*   __restrict__ src,
        const int*   __restrict__ dst,
        const float* __restrict__ bias,
        float* __restrict__ out,
        int n) {
    extern __shared__ float sx[];   // 57344 floats

    const int stride = gridDim.x * blockDim.x;
    const int gtid   = blockIdx.x * blockDim.x + threadIdx.x;

    // Prologue A: out = bias (coalesced, once across the whole grid).
    for (int i = gtid; i < NODES; i += stride)
        out[i] = bias[i];

    // Prologue B: cooperative coalesced load of x[0 .. SMEM_NODES) into smem.
    {
        const float4* x4 = reinterpret_cast<const float4*>(x);
        float4* sx4 = reinterpret_cast<float4*>(sx);
        for (int i = threadIdx.x; i < SMEM_NODES / 4; i += blockDim.x)
            sx4[i] = x4[i];
    }
    __syncthreads();

    const int n4 = n >> 2;
    const float4* __restrict__ ew4 = reinterpret_cast<const float4*>(ew);
    const int4*   __restrict__ s4  = reinterpret_cast<const int4*>(src);
    const int4*   __restrict__ d4  = reinterpret_cast<const int4*>(dst);

    // Replica fixed per warp, decorrelated across warps AND CTAs.
    const int warp = threadIdx.x >> 5;
    float* rep = g_rep + ((blockIdx.x + warp) & (REPLICAS - 1)) * NODES;

    for (int i = gtid; i < n4; i += stride) {
        int4   s = __ldcs(&s4[i]);
        float4 w = __ldcs(&ew4[i]);
        int4   d = __ldcs(&d4[i]);

        // Gather: smem for the low 87.5% of node ids, global for the rest.
        int c0 = (s.x < SMEM_NODES) ? s.x : 0;
        int c1 = (s.y < SMEM_NODES) ? s.y : 0;
        int c2 = (s.z < SMEM_NODES) ? s.z : 0;
        int c3 = (s.w < SMEM_NODES) ? s.w : 0;
        float x0 = sx[c0];
        float x1 = sx[c1];
        float x2 = sx[c2];
        float x3 = sx[c3];
        if (s.x >= SMEM_NODES) x0 = __ldg(&x[s.x]);
        if (s.y >= SMEM_NODES) x1 = __ldg(&x[s.y]);
        if (s.z >= SMEM_NODES) x2 = __ldg(&x[s.z]);
        if (s.w >= SMEM_NODES) x3 = __ldg(&x[s.w]);

        atomicAdd(&rep[d.x], w.x * x0);
        atomicAdd(&rep[d.y], w.y * x1);
        atomicAdd(&rep[d.z], w.z * x2);
        atomicAdd(&rep[d.w], w.w * x3);
    }

    // Tail (n % 4)
    for (int e = (n4 << 2) + gtid; e < n; e += stride) {
        int s = src[e];
        float xv = (s < SMEM_NODES) ? sx[s] : __ldg(&x[s]);
        atomicAdd(&rep[dst[e]], ew[e] * xv);
    }
}

// Group-major mapping: g = t >> 14 (replica group 0..1), i = t & 16383
// (float4 column). Consecutive lanes -> consecutive columns of the SAME
// replica array (coalesced 512B warp loads). Sums replicas [8g .. 8g+7] at
// column i (MLP=8), re-zeroes them (restores the BSS "g_rep==0 at scatter
// entry" invariant), REDG-adds the partial into out (out holds bias).
__global__ __launch_bounds__(256) void reduce_rezero_kernel(float* __restrict__ out) {
    int t = blockIdx.x * blockDim.x + threadIdx.x;
    if (t >= COLS4 * RGROUPS) return;
    int g = t >> 14;          // replica group
    int i = t & (COLS4 - 1);  // float4 column

    float4 v[RPG];
#pragma unroll
    for (int r = 0; r < RPG; ++r)
        v[r] = *(reinterpret_cast<const float4*>(&g_rep[(g * RPG + r) * NODES]) + i);

#pragma unroll
    for (int r = 0; r < RPG; ++r)
        *(reinterpret_cast<float4*>(&g_rep[(g * RPG + r) * NODES]) + i) =
            make_float4(0.f, 0.f, 0.f, 0.f);

    float4 acc = v[0];
#pragma unroll
    for (int r = 1; r < RPG; ++r) {
        acc.x += v[r].x; acc.y += v[r].y; acc.z += v[r].z; acc.w += v[r].w;
    }

    float* o = out + 4 * i;
    atomicAdd(o + 0, acc.x);
    atomicAdd(o + 1, acc.y);
    atomicAdd(o + 2, acc.z);
    atomicAdd(o + 3, acc.w);
}

// Generic fallback for unexpected shapes (does not touch g_rep).
__global__ __launch_bounds__(256) void scatter_fallback_kernel(
        const float* __restrict__ x,
        const float* __restrict__ ew,
        const int*   __restrict__ src,
        const int*   __restrict__ dst,
        float* __restrict__ out,
        int n) {
    const int stride = gridDim.x * blockDim.x;
    for (int e = blockIdx.x * blockDim.x + threadIdx.x; e < n; e += stride) {
        atomicAdd(&out[dst[e]], ew[e] * __ldg(&x[src[e]]));
    }
}

__global__ void init_out_kernel(const float* __restrict__ bias,
                                float* __restrict__ out, int n) {
    int i = blockIdx.x * blockDim.x + threadIdx.x;
    if (i < n) out[i] = bias[i];
}

extern "C" void kernel_launch(void* const* d_in, const int* in_sizes, int n_in,
                              void* d_out, int out_size) {
    const float* x    = (const float*)d_in[0];
    const float* ew   = (const float*)d_in[1];
    const float* bias = (const float*)d_in[2];
    const int*   src  = (const int*)d_in[3];
    const int*   dst  = (const int*)d_in[4];
    float* out = (float*)d_out;

    const int n_nodes = in_sizes[0];
    const int n_edges = in_sizes[1];

    if (n_nodes == NODES) {
        // 1) scatter into replicas; prologue sets out = bias.
        //    (g_rep is zero: BSS on first call, re-zeroed by reduce after.)
        {
            static bool attr_set = false;
            if (!attr_set) {
                cudaFuncSetAttribute(scatter_smem_rep_kernel,
                                     cudaFuncAttributeMaxDynamicSharedMemorySize,
                                     SMEM_BYTES);
                attr_set = true;
            }
            scatter_smem_rep_kernel<<<148, 1024, SMEM_BYTES>>>(
                x, ew, src, dst, bias, out, n_edges);
        }
        // 2) out += per-group replica sums; rezero replicas.
        {
            int total = COLS4 * RGROUPS;   // 32768 threads
            reduce_rezero_kernel<<<total / 256, 256>>>(out);
        }
    } else {
        init_out_kernel<<<(n_nodes + 255) / 256, 256>>>(bias, out, n_nodes);
        int threads = 256;
        int blocks  = 2048;
        int max_blocks = (n_edges + threads - 1) / threads;
        if (blocks > max_blocks) blocks = max_blocks;
        if (blocks < 1) blocks = 1;
        scatter_fallback_kernel<<<blocks, threads>>>(x, ew, src, dst, out, n_edges);
    }
}

// round 17
// speedup vs baseline: 1.0186x; 1.0186x over previous
#include <cuda_runtime.h>
#include <cuda_bf16.h>

// Inputs (metadata order):
//   d_in[0] = x            float32 [65536]
//   d_in[1] = edge_weights float32 [16777216]
//   d_in[2] = bias         float32 [65536]
//   d_in[3] = src          int32   [16777216]
//   d_in[4] = dst          int32   [16777216]
// Output: out[i] = bias[i] + sum_{e: dst[e]==i} x[src[e]]*edge_weights[e]
//
// FINAL (= R15, measured 105.6us; R16's RPG=8 reduce regressed, reverted):
//  - Scatter (~98us, at the LTS fp32-RMW cap ~101us): grid-stride unroll-4,
//    REPLICAS=16 (measured contention knee: 8 too few, 32 no better),
//    __ldcs on the three streams, 224KB of x in smem (87.5% of gathers are
//    LDS, rest LDG), bias folded into the prologue (out = bias).
//  - Reduce (6.1us, measured optimum of 6 shapes): RGROUPS=4 x RPG=4,
//    group-major coalesced (consecutive lanes -> consecutive columns of one
//    replica array), MLP=4, inline rezero (preserves the BSS "g_rep==0 at
//    scatter entry" invariant -> no standalone zero kernel), REDG partials
//    into out.

#define NODES      65536
#define REPLICAS   16
#define RGROUPS    4
#define RPG        (REPLICAS / RGROUPS)   // 4 replicas per thread
#define COLS4      (NODES / 4)            // 16384 float4 columns
#define SMEM_NODES 57344                  // 224KB of x in smem
#define SMEM_BYTES (SMEM_NODES * 4)

__device__ float g_rep[REPLICAS * NODES];   // 4MB scratch, zero-initialized

__global__ __launch_bounds__(1024) void scatter_smem_rep_kernel(
        const float* __restrict__ x,
        const float* __restrict__ ew,
        const int*   __restrict__ src,
        const int*   __restrict__ dst,
        const float* __restrict__ bias,
        float* __restrict__ out,
        int n) {
    extern __shared__ float sx[];   // 57344 floats

    const int stride = gridDim.x * blockDim.x;
    const int gtid   = blockIdx.x * blockDim.x + threadIdx.x;

    // Prologue A: out = bias (coalesced, once across the whole grid).
    for (int i = gtid; i < NODES; i += stride)
        out[i] = bias[i];

    // Prologue B: cooperative coalesced load of x[0 .. SMEM_NODES) into smem.
    {
        const float4* x4 = reinterpret_cast<const float4*>(x);
        float4* sx4 = reinterpret_cast<float4*>(sx);
        for (int i = threadIdx.x; i < SMEM_NODES / 4; i += blockDim.x)
            sx4[i] = x4[i];
    }
    __syncthreads();

    const int n4 = n >> 2;
    const float4* __restrict__ ew4 = reinterpret_cast<const float4*>(ew);
    const int4*   __restrict__ s4  = reinterpret_cast<const int4*>(src);
    const int4*   __restrict__ d4  = reinterpret_cast<const int4*>(dst);

    // Replica fixed per warp, decorrelated across warps AND CTAs.
    const int warp = threadIdx.x >> 5;
    float* rep = g_rep + ((blockIdx.x + warp) & (REPLICAS - 1)) * NODES;

    for (int i = gtid; i < n4; i += stride) {
        int4   s = __ldcs(&s4[i]);
        float4 w = __ldcs(&ew4[i]);
        int4   d = __ldcs(&d4[i]);

        // Gather: smem for the low 87.5% of node ids, global for the rest.
        int c0 = (s.x < SMEM_NODES) ? s.x : 0;
        int c1 = (s.y < SMEM_NODES) ? s.y : 0;
        int c2 = (s.z < SMEM_NODES) ? s.z : 0;
        int c3 = (s.w < SMEM_NODES) ? s.w : 0;
        float x0 = sx[c0];
        float x1 = sx[c1];
        float x2 = sx[c2];
        float x3 = sx[c3];
        if (s.x >= SMEM_NODES) x0 = __ldg(&x[s.x]);
        if (s.y >= SMEM_NODES) x1 = __ldg(&x[s.y]);
        if (s.z >= SMEM_NODES) x2 = __ldg(&x[s.z]);
        if (s.w >= SMEM_NODES) x3 = __ldg(&x[s.w]);

        atomicAdd(&rep[d.x], w.x * x0);
        atomicAdd(&rep[d.y], w.y * x1);
        atomicAdd(&rep[d.z], w.z * x2);
        atomicAdd(&rep[d.w], w.w * x3);
    }

    // Tail (n % 4)
    for (int e = (n4 << 2) + gtid; e < n; e += stride) {
        int s = src[e];
        float xv = (s < SMEM_NODES) ? sx[s] : __ldg(&x[s]);
        atomicAdd(&rep[dst[e]], ew[e] * xv);
    }
}

// Group-major mapping: g = t >> 14 (replica group 0..3), i = t & 16383
// (float4 column). Consecutive lanes -> consecutive columns of the SAME
// replica array (coalesced 512B warp loads). Sums replicas [4g .. 4g+3] at
// column i (MLP=4), re-zeroes them (restores the BSS "g_rep==0 at scatter
// entry" invariant), REDG-adds the partial into out (out holds bias).
__global__ __launch_bounds__(256) void reduce_rezero_kernel(float* __restrict__ out) {
    int t = blockIdx.x * blockDim.x + threadIdx.x;
    if (t >= COLS4 * RGROUPS) return;
    int g = t >> 14;          // replica group
    int i = t & (COLS4 - 1);  // float4 column

    float4 v[RPG];
#pragma unroll
    for (int r = 0; r < RPG; ++r)
        v[r] = *(reinterpret_cast<const float4*>(&g_rep[(g * RPG + r) * NODES]) + i);

#pragma unroll
    for (int r = 0; r < RPG; ++r)
        *(reinterpret_cast<float4*>(&g_rep[(g * RPG + r) * NODES]) + i) =
            make_float4(0.f, 0.f, 0.f, 0.f);

    float4 acc = v[0];
#pragma unroll
    for (int r = 1; r < RPG; ++r) {
        acc.x += v[r].x; acc.y += v[r].y; acc.z += v[r].z; acc.w += v[r].w;
    }

    float* o = out + 4 * i;
    atomicAdd(o + 0, acc.x);
    atomicAdd(o + 1, acc.y);
    atomicAdd(o + 2, acc.z);
    atomicAdd(o + 3, acc.w);
}

// Generic fallback for unexpected shapes (does not touch g_rep).
__global__ __launch_bounds__(256) void scatter_fallback_kernel(
        const float* __restrict__ x,
        const float* __restrict__ ew,
        const int*   __restrict__ src,
        const int*   __restrict__ dst,
        float* __restrict__ out,
        int n) {
    const int stride = gridDim.x * blockDim.x;
    for (int e = blockIdx.x * blockDim.x + threadIdx.x; e < n; e += stride) {
        atomicAdd(&out[dst[e]], ew[e] * __ldg(&x[src[e]]));
    }
}

__global__ void init_out_kernel(const float* __restrict__ bias,
                                float* __restrict__ out, int n) {
    int i = blockIdx.x * blockDim.x + threadIdx.x;
    if (i < n) out[i] = bias[i];
}

extern "C" void kernel_launch(void* const* d_in, const int* in_sizes, int n_in,
                              void* d_out, int out_size) {
    const float* x    = (const float*)d_in[0];
    const float* ew   = (const float*)d_in[1];
    const float* bias = (const float*)d_in[2];
    const int*   src  = (const int*)d_in[3];
    const int*   dst  = (const int*)d_in[4];
    float* out = (float*)d_out;

    const int n_nodes = in_sizes[0];
    const int n_edges = in_sizes[1];

    if (n_nodes == NODES) {
        // 1) scatter into replicas; prologue sets out = bias.
        //    (g_rep is zero: BSS on first call, re-zeroed by reduce after.)
        {
            static bool attr_set = false;
            if (!attr_set) {
                cudaFuncSetAttribute(scatter_smem_rep_kernel,
                                     cudaFuncAttributeMaxDynamicSharedMemorySize,
                                     SMEM_BYTES);
                attr_set = true;
            }
            scatter_smem_rep_kernel<<<148, 1024, SMEM_BYTES>>>(
                x, ew, src, dst, bias, out, n_edges);
        }
        // 2) out += per-group replica sums; rezero replicas.
        {
            int total = COLS4 * RGROUPS;   // 65536 threads
            reduce_rezero_kernel<<<total / 256, 256>>>(out);
        }
    } else {
        init_out_kernel<<<(n_nodes + 255) / 256, 256>>>(bias, out, n_nodes);
        int threads = 256;
        int blocks  = 2048;
        int max_blocks = (n_edges + threads - 1) / threads;
        if (blocks > max_blocks) blocks = max_blocks;
        if (blocks < 1) blocks = 1;
        scatter_fallback_kernel<<<blocks, threads>>>(x, ew, src, dst, out, n_edges);
    }
}